// round 16
// baseline (speedup 1.0000x reference)
#include <cuda_runtime.h>
#include <cuda_fp16.h>
#include <cstdint>

#define B2     2
#define CH     192
#define C3     (3*CH)
#define HEADS  4
#define HD     48
#define NSP    4096
#define L2E    1.44269504f

#define QKSTR 56   // half stride: 7 16B-chunks (odd mod 8) -> ldmatrix conflict-free
#define VSTR  72   // 9 chunks
#define CSTR  40   // conv tiles: 5 chunks
#define ORST  52   // O-staging stride (52 ≡ 20 mod 32 -> bank-bijective)

// ---------------- scratch ----------------
__device__ float  g_qkv [B2 * C3 * NSP];
__device__ float  g_qkv2[B2 * C3 * NSP];
__device__ float  g_att [B2 * CH * NSP];
__device__ __half g_qh  [B2 * HEADS * NSP * HD];
__device__ __half g_kh  [B2 * HEADS * NSP * HD];
__device__ __half g_vh  [B2 * CH * NSP];
__device__ __half g_wqh [C3 * CH];   // qkv weight fp16 hi
__device__ __half g_wql [C3 * CH];   // qkv weight fp16 lo
__device__ __half g_wph [CH * CH];   // proj weight fp16 hi
__device__ __half g_wpl [CH * CH];   // proj weight fp16 lo

// ---------------- asm helpers ----------------
__device__ __forceinline__ uint32_t sptr(const void* p) {
    return (uint32_t)__cvta_generic_to_shared(p);
}
__device__ __forceinline__ void ldsm_x4(uint32_t& r0, uint32_t& r1, uint32_t& r2, uint32_t& r3,
                                        const __half* p) {
    asm volatile("ldmatrix.sync.aligned.m8n8.x4.shared.b16 {%0,%1,%2,%3}, [%4];"
                 : "=r"(r0), "=r"(r1), "=r"(r2), "=r"(r3) : "r"(sptr(p)));
}
__device__ __forceinline__ void mma16816(float c[4],
                                         uint32_t a0, uint32_t a1, uint32_t a2, uint32_t a3,
                                         uint32_t b0, uint32_t b1) {
    asm volatile(
        "mma.sync.aligned.m16n8k16.row.col.f32.f16.f16.f32 "
        "{%0,%1,%2,%3}, {%4,%5,%6,%7}, {%8,%9}, {%0,%1,%2,%3};"
        : "+f"(c[0]), "+f"(c[1]), "+f"(c[2]), "+f"(c[3])
        : "r"(a0), "r"(a1), "r"(a2), "r"(a3), "r"(b0), "r"(b1));
}
__device__ __forceinline__ uint32_t cvt2(float hi, float lo) {
    uint32_t r;
    asm("cvt.rn.f16x2.f32 %0, %1, %2;" : "=r"(r) : "f"(hi), "f"(lo));
    return r;
}
__device__ __forceinline__ uint32_t ex2h2(uint32_t x) {
    uint32_t r;
    asm("ex2.approx.f16x2 %0, %1;" : "=r"(r) : "r"(x));
    return r;
}
__device__ __forceinline__ uint32_t hadd2(uint32_t a, uint32_t b) {
    uint32_t r;
    asm("add.rn.f16x2 %0, %1, %2;" : "=r"(r) : "r"(a), "r"(b));
    return r;
}
__device__ __forceinline__ float2 h22f2(uint32_t u) {
    __half2 h = *reinterpret_cast<__half2*>(&u);
    return __half22float2(h);
}
__device__ __forceinline__ void split4(float4 f, uint2& hi, uint2& lo) {
    hi = make_uint2(cvt2(f.y, f.x), cvt2(f.w, f.z));
    float2 g0 = h22f2(hi.x), g1 = h22f2(hi.y);
    lo = make_uint2(cvt2(f.y - g0.y, f.x - g0.x), cvt2(f.w - g1.y, f.z - g1.x));
}
__device__ __forceinline__ void cp16(const __half* smem_dst, const __half* gsrc) {
    asm volatile("cp.async.cg.shared.global [%0], [%1], 16;"
                 :: "r"(sptr(smem_dst)), "l"(gsrc));
}
__device__ __forceinline__ void cp_commit() { asm volatile("cp.async.commit_group;"); }
__device__ __forceinline__ void cp_wait0()  { asm volatile("cp.async.wait_group 0;"); }

// ---------------- weight prep: fp32 W -> fp16 hi/lo (one-time) ----------------
// grid: (elems/1024), block 256, one float4 per thread
__global__ void __launch_bounds__(256) wprep_kernel(
    const float* __restrict__ W, __half* __restrict__ Wh, __half* __restrict__ Wl,
    int elems4)
{
    const int i = blockIdx.x * 256 + threadIdx.x;
    if (i >= elems4) return;
    float4 f = *(const float4*)(W + i * 4);
    uint2 hi, lo;
    split4(f, hi, lo);
    *(uint2*)(Wh + i * 4) = hi;
    *(uint2*)(Wl + i * 4) = lo;
}

// ---------------- 1x1 conv, W pre-split (cp.async), X split in-loop ----------------
// grid (NSP/64, OC/64, B2), block 256
__global__ void __launch_bounds__(256) conv1x1_tc_kernel(
    const float* __restrict__ X,
    const __half* __restrict__ Whg, const __half* __restrict__ Wlg,
    const float* __restrict__ bias, float* __restrict__ Cout,
    int OC, int IC)
{
    __shared__ __align__(16) __half Whs[64 * CSTR];
    __shared__ __align__(16) __half Wls[64 * CSTR];
    __shared__ __align__(16) __half Xhs[64 * CSTR];
    __shared__ __align__(16) __half Xls[64 * CSTR];

    const int t    = threadIdx.x;
    const int lane = t & 31;
    const int wid  = t >> 5;
    const int o0w  = (wid & 3) * 16;
    const int n0w  = (wid >> 2) * 32;
    const int r    = lane >> 2;
    const int cc   = lane & 3;

    const int n0 = blockIdx.x * 64;
    const int o0 = blockIdx.y * 64;
    const int b  = blockIdx.z;

    const float* Xb = X + ((size_t)b * IC) * NSP + n0;

    const int nX = t & 63;
    const int cg = (t >> 6) * 4;

    // W cp.async coords: 512 chunks (Wh 256 + Wl 256), 2 per thread
    // idx = t + e*256; buf = idx>>8; row = (idx&255)>>2; c8 = (idx&3)*8
    float sacc[4][4];
#pragma unroll
    for (int nt = 0; nt < 4; ++nt)
#pragma unroll
        for (int e = 0; e < 4; ++e) sacc[nt][e] = 0.f;

    for (int c0 = 0; c0 < IC; c0 += 32) {
        // ---- W tiles via cp.async (pre-split fp16, no cvt) ----
#pragma unroll
        for (int e = 0; e < 2; ++e) {
            int idx  = t + e * 256;
            int row  = (idx & 255) >> 2;
            int c8   = (idx & 3) * 8;
            const __half* src = ((idx < 256) ? Whg : Wlg)
                              + (size_t)(o0 + row) * IC + c0 + c8;
            __half* dst = ((idx < 256) ? Whs : Wls) + row * CSTR + c8;
            cp16(dst, src);
        }
        cp_commit();

        // ---- X tile transposed + split (unchanged) ----
#pragma unroll
        for (int e = 0; e < 2; ++e) {
            int c = cg + e * 16;
            float4 f;
            f.x = Xb[(size_t)(c0 + c + 0) * NSP + nX];
            f.y = Xb[(size_t)(c0 + c + 1) * NSP + nX];
            f.z = Xb[(size_t)(c0 + c + 2) * NSP + nX];
            f.w = Xb[(size_t)(c0 + c + 3) * NSP + nX];
            uint2 hi, lo;
            split4(f, hi, lo);
            *(uint2*)&Xhs[nX * CSTR + c] = hi;
            *(uint2*)&Xls[nX * CSTR + c] = lo;
        }
        cp_wait0();
        __syncthreads();

#pragma unroll
        for (int ks = 0; ks < 2; ++ks) {
            const int arow = (o0w + (lane & 15)) * CSTR + ks * 16 + ((lane >> 4) << 3);
            uint32_t ah0, ah1, ah2, ah3, al0, al1, al2, al3;
            ldsm_x4(ah0, ah1, ah2, ah3, &Whs[arow]);
            ldsm_x4(al0, al1, al2, al3, &Wls[arow]);
#pragma unroll
            for (int p = 0; p < 2; ++p) {
                const int brow = (n0w + p * 16 + ((lane >> 4) << 3) + (lane & 7)) * CSTR
                               + ks * 16 + (lane & 8);
                uint32_t bh0, bh1, bh2, bh3, bl0, bl1, bl2, bl3;
                ldsm_x4(bh0, bh1, bh2, bh3, &Xhs[brow]);
                ldsm_x4(bl0, bl1, bl2, bl3, &Xls[brow]);
                mma16816(sacc[2 * p],     ah0, ah1, ah2, ah3, bh0, bh1);
                mma16816(sacc[2 * p + 1], ah0, ah1, ah2, ah3, bh2, bh3);
                mma16816(sacc[2 * p],     ah0, ah1, ah2, ah3, bl0, bl1);
                mma16816(sacc[2 * p + 1], ah0, ah1, ah2, ah3, bl2, bl3);
                mma16816(sacc[2 * p],     al0, al1, al2, al3, bh0, bh1);
                mma16816(sacc[2 * p + 1], al0, al1, al2, al3, bh2, bh3);
            }
        }
        __syncthreads();
    }

    const int o_lo = o0 + o0w + r;
    const int o_hi = o_lo + 8;
    const float blo = bias[o_lo];
    const float bhi = bias[o_hi];
    float* out_lo = Cout + ((size_t)b * OC + o_lo) * NSP + n0 + n0w;
    float* out_hi = Cout + ((size_t)b * OC + o_hi) * NSP + n0 + n0w;
#pragma unroll
    for (int nt = 0; nt < 4; ++nt) {
        int n = nt * 8 + 2 * cc;
        *(float2*)(out_lo + n) = make_float2(sacc[nt][0] + blo, sacc[nt][1] + blo);
        *(float2*)(out_hi + n) = make_float2(sacc[nt][2] + bhi, sacc[nt][3] + bhi);
    }
}

// ---------------- 3x3 depthwise conv, VECTORIZED: 4 pixels/thread (R15) --------------
__global__ void __launch_bounds__(256) dwconv_kernel(
    const float* __restrict__ in, const float* __restrict__ wdw,
    const float* __restrict__ bias, float* __restrict__ out, __half* __restrict__ vh)
{
    const int bc = blockIdx.x;
    const int ch = bc % C3;
    const int b  = bc / C3;
    const float* p = in + (size_t)bc * NSP;

    float w9[9];
#pragma unroll
    for (int i = 0; i < 9; ++i) w9[i] = wdw[ch * 9 + i];

    const int n4 = (blockIdx.y * 256 + threadIdx.x) * 4;
    const int y  = n4 >> 6;
    const int x0 = n4 & 63;
    const bool has_l = (x0 > 0);
    const bool has_r = (x0 + 4 < 64);

    const float bv = bias[ch];
    float acc[4] = {bv, bv, bv, bv};

#pragma unroll
    for (int dy = -1; dy <= 1; ++dy) {
        const int yy = y + dy;
        if (yy < 0 || yy > 63) continue;
        const float* row = p + yy * 64 + x0;
        float4 c4 = *(const float4*)row;
        float vl = has_l ? row[-1] : 0.f;
        float vr = has_r ? row[4]  : 0.f;
        const float wl = w9[(dy + 1) * 3 + 0];
        const float wc = w9[(dy + 1) * 3 + 1];
        const float wr = w9[(dy + 1) * 3 + 2];
        acc[0] += wl * vl;   acc[0] += wc * c4.x; acc[0] += wr * c4.y;
        acc[1] += wl * c4.x; acc[1] += wc * c4.y; acc[1] += wr * c4.z;
        acc[2] += wl * c4.y; acc[2] += wc * c4.z; acc[2] += wr * c4.w;
        acc[3] += wl * c4.z; acc[3] += wc * c4.w; acc[3] += wr * vr;
    }

    if (ch < 2 * CH) {
        *(float4*)(out + (size_t)bc * NSP + n4) =
            make_float4(acc[0], acc[1], acc[2], acc[3]);
    } else {
        uint2 hv = make_uint2(cvt2(acc[1], acc[0]), cvt2(acc[3], acc[2]));
        *(uint2*)(vh + ((size_t)b * CH + (ch - 2 * CH)) * NSP + n4) = hv;
    }
}

// ---------------- single-pass L2 norm -> fp16 [bh][n][48] (R9) ----------------
__global__ void __launch_bounds__(128) normh_kernel(
    const float* __restrict__ qkv, __half* __restrict__ qh, __half* __restrict__ kh,
    const float* __restrict__ temp)
{
    const int which = blockIdx.z;
    const int bh    = blockIdx.y;
    const int b     = bh >> 2;
    const int head  = bh & 3;
    const int n     = blockIdx.x * 128 + threadIdx.x;

    const float* p = qkv + ((size_t)(b * C3) + which * CH + head * HD) * NSP + n;

    float v[HD];
    float s = 0.f;
#pragma unroll
    for (int d = 0; d < HD; ++d) {
        v[d] = p[(size_t)d * NSP];
        s += v[d] * v[d];
    }
    const float sc = (which ? 1.0f : temp[head] * L2E) / fmaxf(sqrtf(s), 1e-12f);

    __half* o = (which ? kh : qh) + ((size_t)bh * NSP + n) * HD;
#pragma unroll
    for (int g = 0; g < 6; ++g) {
        float a0 = v[g * 8 + 0] * sc, a1 = v[g * 8 + 1] * sc;
        float a2 = v[g * 8 + 2] * sc, a3 = v[g * 8 + 3] * sc;
        float a4 = v[g * 8 + 4] * sc, a5 = v[g * 8 + 5] * sc;
        float a6 = v[g * 8 + 6] * sc, a7 = v[g * 8 + 7] * sc;
        *(uint4*)(o + g * 8) = make_uint4(cvt2(a1, a0), cvt2(a3, a2), cvt2(a5, a4), cvt2(a7, a6));
    }
}

// ---------------- flash attention (R9/R15 verbatim) ----------------
__global__ void __launch_bounds__(256, 2) attn_kernel(
    const __half* __restrict__ qh, const __half* __restrict__ kh,
    const __half* __restrict__ vh, const float* __restrict__ temp,
    float* __restrict__ out)
{
    __shared__ __align__(16) char arena[43008];
    __half* Qs = (__half*)arena;
    __half* KsBuf[2] = { (__half*)(arena + 14336), (__half*)(arena + 21504) };
    __half* VsBuf[2] = { (__half*)(arena + 28672), (__half*)(arena + 35584) };
    float*  lred = (float*)(arena + 42496);
    float*  Ored = (float*)arena;

    const int t    = threadIdx.x;
    const int lane = t & 31;
    const int wid  = t >> 5;
    const int wi   = wid & 3;
    const int wj   = wid >> 2;
    const int i0   = wi * 32;
    const int r    = lane >> 2;
    const int cc   = lane & 3;

    const int bh   = blockIdx.y;
    const int b    = bh >> 2;
    const int head = bh & 3;
    const int n0   = blockIdx.x * 128;

    const __half* qb = qh + (size_t)bh * NSP * HD;
    const __half* kb = kh + (size_t)bh * NSP * HD;
    const __half* vb = vh + ((size_t)b * CH + head * HD) * NSP;
    const float   cbias = fabsf(temp[head]) * L2E;

#pragma unroll
    for (int e = 0; e < 3; ++e) {
        int ch = t + e * 256, row = ch / 6, c = (ch % 6) * 8;
        cp16(&Qs[row * QKSTR + c], qb + ((size_t)(n0 + row)) * HD + c);
    }
    {
        int row = t / 6, c = (t % 6) * 8;
        cp16(&KsBuf[0][row * QKSTR + c], kb + (size_t)row * HD + c);
    }
    if (t < 128) {
        int ch = t + 256, row = ch / 6, c = (ch % 6) * 8;
        cp16(&KsBuf[0][row * QKSTR + c], kb + (size_t)row * HD + c);
    }
    {
        int row = t >> 3, c = (t & 7) * 8;
        cp16(&VsBuf[0][row * VSTR + c], vb + (size_t)row * NSP + c);
    }
    if (t < 128) {
        int ch = t + 256, row = ch >> 3, c = (ch & 7) * 8;
        cp16(&VsBuf[0][row * VSTR + c], vb + (size_t)row * NSP + c);
    }
    cp_commit();

    float oacc[2][6][4];
#pragma unroll
    for (int mt = 0; mt < 2; ++mt)
#pragma unroll
        for (int nt = 0; nt < 6; ++nt)
#pragma unroll
            for (int e = 0; e < 4; ++e) oacc[mt][nt][e] = 0.f;
    float l_lo[2] = {0.f, 0.f}, l_hi[2] = {0.f, 0.f};

    uint32_t qa[2][3][4];

    const int krow0 = t / 6,          kc0 = (t % 6) * 8;
    const int krow1 = (t + 256) / 6,  kc1 = ((t + 256) % 6) * 8;
    const int vrow0 = t >> 3,         vc0 = (t & 7) * 8;
    const int vrow1 = (t + 256) >> 3, vc1 = ((t + 256) & 7) * 8;

    for (int it = 0; it < NSP / 64; ++it) {
        const int cur = it & 1;
        const __half* Kc = KsBuf[cur];
        const __half* Vc = VsBuf[cur];
        const bool has_next = (it < NSP / 64 - 1);

        cp_wait0();
        __syncthreads();

        if (it == 0) {
#pragma unroll
            for (int mt = 0; mt < 2; ++mt)
#pragma unroll
                for (int ks = 0; ks < 3; ++ks)
                    ldsm_x4(qa[mt][ks][0], qa[mt][ks][1], qa[mt][ks][2], qa[mt][ks][3],
                            &Qs[(i0 + mt * 16 + (lane & 15)) * QKSTR + ks * 16 + ((lane >> 4) << 3)]);
        }

        if (has_next) {
            const int nb = cur ^ 1;
            const int m0n = (it + 1) * 64;
            cp16(&KsBuf[nb][krow0 * QKSTR + kc0], kb + ((size_t)(m0n + krow0)) * HD + kc0);
            if (t < 128)
                cp16(&KsBuf[nb][krow1 * QKSTR + kc1], kb + ((size_t)(m0n + krow1)) * HD + kc1);
            cp16(&VsBuf[nb][vrow0 * VSTR + vc0], vb + (size_t)vrow0 * NSP + m0n + vc0);
            if (t < 128)
                cp16(&VsBuf[nb][vrow1 * VSTR + vc1], vb + (size_t)vrow1 * NSP + m0n + vc1);
            cp_commit();
        }

        float sacc[2][4][4];
#pragma unroll
        for (int mt = 0; mt < 2; ++mt)
#pragma unroll
            for (int jj = 0; jj < 4; ++jj)
#pragma unroll
                for (int e = 0; e < 4; ++e) sacc[mt][jj][e] = 0.f;

#pragma unroll
        for (int ks = 0; ks < 3; ++ks) {
#pragma unroll
            for (int p = 0; p < 2; ++p) {
                uint32_t b0, b1, b2, b3;
                int row = wj * 32 + p * 16 + ((lane >> 4) << 3) + (lane & 7);
                int col = ks * 16 + (lane & 8);
                ldsm_x4(b0, b1, b2, b3, &Kc[row * QKSTR + col]);
#pragma unroll
                for (int mt = 0; mt < 2; ++mt) {
                    mma16816(sacc[mt][2 * p],     qa[mt][ks][0], qa[mt][ks][1],
                                                  qa[mt][ks][2], qa[mt][ks][3], b0, b1);
                    mma16816(sacc[mt][2 * p + 1], qa[mt][ks][0], qa[mt][ks][1],
                                                  qa[mt][ks][2], qa[mt][ks][3], b2, b3);
                }
            }
        }

        uint32_t plo[2][4], phi[2][4];
#pragma unroll
        for (int mt = 0; mt < 2; ++mt) {
            uint32_t sum_lo = 0, sum_hi = 0;
#pragma unroll
            for (int jj = 0; jj < 4; ++jj) {
                plo[mt][jj] = ex2h2(cvt2(sacc[mt][jj][1] - cbias, sacc[mt][jj][0] - cbias));
                phi[mt][jj] = ex2h2(cvt2(sacc[mt][jj][3] - cbias, sacc[mt][jj][2] - cbias));
                sum_lo = hadd2(sum_lo, plo[mt][jj]);
                sum_hi = hadd2(sum_hi, phi[mt][jj]);
            }
            float2 f0 = h22f2(sum_lo); l_lo[mt] += f0.x + f0.y;
            float2 f1 = h22f2(sum_hi); l_hi[mt] += f1.x + f1.y;
        }

#pragma unroll
        for (int nt = 0; nt < 6; ++nt) {
            uint32_t b0, b1, b2, b3;
            ldsm_x4(b0, b1, b2, b3,
                    &Vc[(nt * 8 + (lane & 7)) * VSTR + wj * 32 + ((lane >> 3) & 3) * 8]);
#pragma unroll
            for (int mt = 0; mt < 2; ++mt) {
                mma16816(oacc[mt][nt], plo[mt][0], phi[mt][0], plo[mt][1], phi[mt][1], b0, b1);
                mma16816(oacc[mt][nt], plo[mt][2], phi[mt][2], plo[mt][3], phi[mt][3], b2, b3);
            }
        }
        __syncthreads();
    }

#pragma unroll
    for (int mt = 0; mt < 2; ++mt) {
        l_lo[mt] += __shfl_xor_sync(0xffffffffu, l_lo[mt], 1);
        l_lo[mt] += __shfl_xor_sync(0xffffffffu, l_lo[mt], 2);
        l_hi[mt] += __shfl_xor_sync(0xffffffffu, l_hi[mt], 1);
        l_hi[mt] += __shfl_xor_sync(0xffffffffu, l_hi[mt], 2);
    }
    if (wj == 1) {
#pragma unroll
        for (int mt = 0; mt < 2; ++mt) {
            const int ib = i0 + mt * 16;
            if (cc == 0) {
                lred[ib + r]     = l_lo[mt];
                lred[ib + r + 8] = l_hi[mt];
            }
#pragma unroll
            for (int nt = 0; nt < 6; ++nt) {
                int d = nt * 8 + 2 * cc;
                *(float2*)&Ored[(ib + r) * ORST + d]     = make_float2(oacc[mt][nt][0], oacc[mt][nt][1]);
                *(float2*)&Ored[(ib + r + 8) * ORST + d] = make_float2(oacc[mt][nt][2], oacc[mt][nt][3]);
            }
        }
    }
    __syncthreads();
    if (wj == 0) {
        float* ob = out + ((size_t)(b * CH) + head * HD) * NSP + n0;
#pragma unroll
        for (int mt = 0; mt < 2; ++mt) {
            const int ib = i0 + mt * 16;
            const float linv_lo = 1.f / (l_lo[mt] + lred[ib + r]);
            const float linv_hi = 1.f / (l_hi[mt] + lred[ib + r + 8]);
#pragma unroll
            for (int nt = 0; nt < 6; ++nt) {
                int d = nt * 8 + 2 * cc;
                float2 p0 = *(const float2*)&Ored[(ib + r) * ORST + d];
                float2 p1 = *(const float2*)&Ored[(ib + r + 8) * ORST + d];
                ob[(size_t)d * NSP + ib + r]           = (oacc[mt][nt][0] + p0.x) * linv_lo;
                ob[(size_t)(d + 1) * NSP + ib + r]     = (oacc[mt][nt][1] + p0.y) * linv_lo;
                ob[(size_t)d * NSP + ib + r + 8]       = (oacc[mt][nt][2] + p1.x) * linv_hi;
                ob[(size_t)(d + 1) * NSP + ib + r + 8] = (oacc[mt][nt][3] + p1.y) * linv_hi;
            }
        }
    }
}

// ---------------- launcher ----------------
extern "C" void kernel_launch(void* const* d_in, const int* in_sizes, int n_in,
                              void* d_out, int out_size)
{
    const float* x      = (const float*)d_in[0];
    const float* w_qkv  = (const float*)d_in[1];
    const float* b_qkv  = (const float*)d_in[2];
    const float* w_dw   = (const float*)d_in[3];
    const float* b_dw   = (const float*)d_in[4];
    const float* w_proj = (const float*)d_in[5];
    const float* b_proj = (const float*)d_in[6];
    const float* temp   = (const float*)d_in[7];
    float* out = (float*)d_out;

    float*  qkv1; cudaGetSymbolAddress((void**)&qkv1, g_qkv);
    float*  qkv2; cudaGetSymbolAddress((void**)&qkv2, g_qkv2);
    float*  att;  cudaGetSymbolAddress((void**)&att,  g_att);
    __half* qhp;  cudaGetSymbolAddress((void**)&qhp,  g_qh);
    __half* khp;  cudaGetSymbolAddress((void**)&khp,  g_kh);
    __half* vhp;  cudaGetSymbolAddress((void**)&vhp,  g_vh);
    __half* wqh;  cudaGetSymbolAddress((void**)&wqh,  g_wqh);
    __half* wql;  cudaGetSymbolAddress((void**)&wql,  g_wql);
    __half* wph;  cudaGetSymbolAddress((void**)&wph,  g_wph);
    __half* wpl;  cudaGetSymbolAddress((void**)&wpl,  g_wpl);

    wprep_kernel<<<(C3 * CH / 4 + 255) / 256, 256>>>(w_qkv, wqh, wql, C3 * CH / 4);
    wprep_kernel<<<(CH * CH / 4 + 255) / 256, 256>>>(w_proj, wph, wpl, CH * CH / 4);
    conv1x1_tc_kernel<<<dim3(NSP / 64, C3 / 64, B2), 256>>>(x, wqh, wql, b_qkv, qkv1, C3, CH);
    dwconv_kernel<<<dim3(B2 * C3, NSP / 1024), 256>>>(qkv1, w_dw, b_dw, qkv2, vhp);
    normh_kernel<<<dim3(NSP / 128, B2 * HEADS, 2), 128>>>(qkv2, qhp, khp, temp);
    attn_kernel<<<dim3(NSP / 128, B2 * HEADS), 256>>>(qhp, khp, vhp, temp, att);
    conv1x1_tc_kernel<<<dim3(NSP / 64, CH / 64, B2), 256>>>(att, wph, wpl, b_proj, out, CH, CH);
}

// round 17
// speedup vs baseline: 1.0156x; 1.0156x over previous
#include <cuda_runtime.h>
#include <cuda_fp16.h>
#include <cstdint>

#define B2     2
#define CH     192
#define C3     (3*CH)
#define HEADS  4
#define HD     48
#define NSP    4096
#define L2E    1.44269504f

#define QKSTR 56   // half stride: 7 16B-chunks (odd mod 8) -> ldmatrix conflict-free
#define VSTR  72   // 9 chunks
#define CSTR  40   // conv tiles: 5 chunks
#define ORST  52   // O-staging stride (52 ≡ 20 mod 32 -> bank-bijective)

// ---------------- scratch ----------------
__device__ float  g_qkv [B2 * C3 * NSP];
__device__ __half g_qk16[B2 * 2 * CH * NSP];   // dw output for q,k (fp16, [b][ch][n])
__device__ float  g_att [B2 * CH * NSP];
__device__ __half g_qh  [B2 * HEADS * NSP * HD];
__device__ __half g_kh  [B2 * HEADS * NSP * HD];
__device__ __half g_vh  [B2 * CH * NSP];

// ---------------- asm helpers ----------------
__device__ __forceinline__ uint32_t sptr(const void* p) {
    return (uint32_t)__cvta_generic_to_shared(p);
}
__device__ __forceinline__ void ldsm_x4(uint32_t& r0, uint32_t& r1, uint32_t& r2, uint32_t& r3,
                                        const __half* p) {
    asm volatile("ldmatrix.sync.aligned.m8n8.x4.shared.b16 {%0,%1,%2,%3}, [%4];"
                 : "=r"(r0), "=r"(r1), "=r"(r2), "=r"(r3) : "r"(sptr(p)));
}
__device__ __forceinline__ void mma16816(float c[4],
                                         uint32_t a0, uint32_t a1, uint32_t a2, uint32_t a3,
                                         uint32_t b0, uint32_t b1) {
    asm volatile(
        "mma.sync.aligned.m16n8k16.row.col.f32.f16.f16.f32 "
        "{%0,%1,%2,%3}, {%4,%5,%6,%7}, {%8,%9}, {%0,%1,%2,%3};"
        : "+f"(c[0]), "+f"(c[1]), "+f"(c[2]), "+f"(c[3])
        : "r"(a0), "r"(a1), "r"(a2), "r"(a3), "r"(b0), "r"(b1));
}
__device__ __forceinline__ uint32_t cvt2(float hi, float lo) {
    uint32_t r;
    asm("cvt.rn.f16x2.f32 %0, %1, %2;" : "=r"(r) : "f"(hi), "f"(lo));
    return r;
}
__device__ __forceinline__ uint32_t ex2h2(uint32_t x) {
    uint32_t r;
    asm("ex2.approx.f16x2 %0, %1;" : "=r"(r) : "r"(x));
    return r;
}
__device__ __forceinline__ uint32_t hadd2(uint32_t a, uint32_t b) {
    uint32_t r;
    asm("add.rn.f16x2 %0, %1, %2;" : "=r"(r) : "r"(a), "r"(b));
    return r;
}
__device__ __forceinline__ float2 h22f2(uint32_t u) {
    __half2 h = *reinterpret_cast<__half2*>(&u);
    return __half22float2(h);
}
__device__ __forceinline__ void split4(float4 f, uint2& hi, uint2& lo) {
    hi = make_uint2(cvt2(f.y, f.x), cvt2(f.w, f.z));
    float2 g0 = h22f2(hi.x), g1 = h22f2(hi.y);
    lo = make_uint2(cvt2(f.y - g0.y, f.x - g0.x), cvt2(f.w - g1.y, f.z - g1.x));
}
__device__ __forceinline__ void cp16(const __half* smem_dst, const __half* gsrc) {
    asm volatile("cp.async.cg.shared.global [%0], [%1], 16;"
                 :: "r"(sptr(smem_dst)), "l"(gsrc));
}
__device__ __forceinline__ void cp_commit() { asm volatile("cp.async.commit_group;"); }
__device__ __forceinline__ void cp_wait0()  { asm volatile("cp.async.wait_group 0;"); }

// ---------------- 1x1 conv as split-fp16 tensor GEMM (R15 verbatim) ----------------
__global__ void __launch_bounds__(256) conv1x1_tc_kernel(
    const float* __restrict__ X, const float* __restrict__ W,
    const float* __restrict__ bias, float* __restrict__ Cout,
    int OC, int IC)
{
    __shared__ __align__(16) __half Wh[64 * CSTR];
    __shared__ __align__(16) __half Wl[64 * CSTR];
    __shared__ __align__(16) __half Xh[64 * CSTR];
    __shared__ __align__(16) __half Xl[64 * CSTR];

    const int t    = threadIdx.x;
    const int lane = t & 31;
    const int wid  = t >> 5;
    const int o0w  = (wid & 3) * 16;
    const int n0w  = (wid >> 2) * 32;
    const int r    = lane >> 2;
    const int cc   = lane & 3;

    const int n0 = blockIdx.x * 64;
    const int o0 = blockIdx.y * 64;
    const int b  = blockIdx.z;

    const float* Xb = X + ((size_t)b * IC) * NSP + n0;

    const int nX = t & 63;
    const int cg = (t >> 6) * 4;

    float sacc[4][4];
#pragma unroll
    for (int nt = 0; nt < 4; ++nt)
#pragma unroll
        for (int e = 0; e < 4; ++e) sacc[nt][e] = 0.f;

    for (int c0 = 0; c0 < IC; c0 += 32) {
#pragma unroll
        for (int e = 0; e < 2; ++e) {
            int idx = t + e * 256;
            int o  = idx >> 3;
            int c4 = (idx & 7) * 4;
            float4 f = *(const float4*)(W + (size_t)(o0 + o) * IC + c0 + c4);
            uint2 hi, lo;
            split4(f, hi, lo);
            *(uint2*)&Wh[o * CSTR + c4] = hi;
            *(uint2*)&Wl[o * CSTR + c4] = lo;
        }
#pragma unroll
        for (int e = 0; e < 2; ++e) {
            int c = cg + e * 16;
            float4 f;
            f.x = Xb[(size_t)(c0 + c + 0) * NSP + nX];
            f.y = Xb[(size_t)(c0 + c + 1) * NSP + nX];
            f.z = Xb[(size_t)(c0 + c + 2) * NSP + nX];
            f.w = Xb[(size_t)(c0 + c + 3) * NSP + nX];
            uint2 hi, lo;
            split4(f, hi, lo);
            *(uint2*)&Xh[nX * CSTR + c] = hi;
            *(uint2*)&Xl[nX * CSTR + c] = lo;
        }
        __syncthreads();

#pragma unroll
        for (int ks = 0; ks < 2; ++ks) {
            const int arow = (o0w + (lane & 15)) * CSTR + ks * 16 + ((lane >> 4) << 3);
            uint32_t ah0, ah1, ah2, ah3, al0, al1, al2, al3;
            ldsm_x4(ah0, ah1, ah2, ah3, &Wh[arow]);
            ldsm_x4(al0, al1, al2, al3, &Wl[arow]);
#pragma unroll
            for (int p = 0; p < 2; ++p) {
                const int brow = (n0w + p * 16 + ((lane >> 4) << 3) + (lane & 7)) * CSTR
                               + ks * 16 + (lane & 8);
                uint32_t bh0, bh1, bh2, bh3, bl0, bl1, bl2, bl3;
                ldsm_x4(bh0, bh1, bh2, bh3, &Xh[brow]);
                ldsm_x4(bl0, bl1, bl2, bl3, &Xl[brow]);
                mma16816(sacc[2 * p],     ah0, ah1, ah2, ah3, bh0, bh1);
                mma16816(sacc[2 * p + 1], ah0, ah1, ah2, ah3, bh2, bh3);
                mma16816(sacc[2 * p],     ah0, ah1, ah2, ah3, bl0, bl1);
                mma16816(sacc[2 * p + 1], ah0, ah1, ah2, ah3, bl2, bl3);
                mma16816(sacc[2 * p],     al0, al1, al2, al3, bh0, bh1);
                mma16816(sacc[2 * p + 1], al0, al1, al2, al3, bh2, bh3);
            }
        }
        __syncthreads();
    }

    const int o_lo = o0 + o0w + r;
    const int o_hi = o_lo + 8;
    const float blo = bias[o_lo];
    const float bhi = bias[o_hi];
    float* out_lo = Cout + ((size_t)b * OC + o_lo) * NSP + n0 + n0w;
    float* out_hi = Cout + ((size_t)b * OC + o_hi) * NSP + n0 + n0w;
#pragma unroll
    for (int nt = 0; nt < 4; ++nt) {
        int n = nt * 8 + 2 * cc;
        *(float2*)(out_lo + n) = make_float2(sacc[nt][0] + blo, sacc[nt][1] + blo);
        *(float2*)(out_hi + n) = make_float2(sacc[nt][2] + bhi, sacc[nt][3] + bhi);
    }
}

// ---------------- 3x3 depthwise conv, vec4; q,k AND v emitted as fp16 ----------------
// grid: (B2*C3, NSP/1024), block 256
__global__ void __launch_bounds__(256) dwconv_kernel(
    const float* __restrict__ in, const float* __restrict__ wdw,
    const float* __restrict__ bias, __half* __restrict__ qk16, __half* __restrict__ vh)
{
    const int bc = blockIdx.x;
    const int ch = bc % C3;
    const int b  = bc / C3;
    const float* p = in + (size_t)bc * NSP;

    float w9[9];
#pragma unroll
    for (int i = 0; i < 9; ++i) w9[i] = wdw[ch * 9 + i];

    const int n4 = (blockIdx.y * 256 + threadIdx.x) * 4;
    const int y  = n4 >> 6;
    const int x0 = n4 & 63;
    const bool has_l = (x0 > 0);
    const bool has_r = (x0 + 4 < 64);

    const float bv = bias[ch];
    float acc[4] = {bv, bv, bv, bv};

#pragma unroll
    for (int dy = -1; dy <= 1; ++dy) {
        const int yy = y + dy;
        if (yy < 0 || yy > 63) continue;
        const float* row = p + yy * 64 + x0;
        float4 c4 = *(const float4*)row;
        float vl = has_l ? row[-1] : 0.f;
        float vr = has_r ? row[4]  : 0.f;
        const float wl = w9[(dy + 1) * 3 + 0];
        const float wc = w9[(dy + 1) * 3 + 1];
        const float wr = w9[(dy + 1) * 3 + 2];
        acc[0] += wl * vl;   acc[0] += wc * c4.x; acc[0] += wr * c4.y;
        acc[1] += wl * c4.x; acc[1] += wc * c4.y; acc[1] += wr * c4.z;
        acc[2] += wl * c4.y; acc[2] += wc * c4.z; acc[2] += wr * c4.w;
        acc[3] += wl * c4.z; acc[3] += wc * c4.w; acc[3] += wr * vr;
    }

    uint2 hv = make_uint2(cvt2(acc[1], acc[0]), cvt2(acc[3], acc[2]));
    if (ch < 2 * CH) {
        *(uint2*)(qk16 + ((size_t)(b * 2 * CH) + ch) * NSP + n4) = hv;
    } else {
        *(uint2*)(vh + ((size_t)b * CH + (ch - 2 * CH)) * NSP + n4) = hv;
    }
}

// ---------------- L2 norm from fp16 input -> fp16 [bh][n][48] ----------------
__global__ void __launch_bounds__(128) normh_kernel(
    const __half* __restrict__ qk16, __half* __restrict__ qh, __half* __restrict__ kh,
    const float* __restrict__ temp)
{
    const int which = blockIdx.z;        // 0 = q, 1 = k
    const int bh    = blockIdx.y;
    const int b     = bh >> 2;
    const int head  = bh & 3;
    const int n     = blockIdx.x * 128 + threadIdx.x;

    const __half* p = qk16 + ((size_t)(b * 2 * CH) + which * CH + head * HD) * NSP + n;

    float v[HD];
    float s = 0.f;
#pragma unroll
    for (int d = 0; d < HD; ++d) {
        v[d] = __half2float(p[(size_t)d * NSP]);
        s += v[d] * v[d];
    }
    const float sc = (which ? 1.0f : temp[head] * L2E) / fmaxf(sqrtf(s), 1e-12f);

    __half* o = (which ? kh : qh) + ((size_t)bh * NSP + n) * HD;
#pragma unroll
    for (int g = 0; g < 6; ++g) {
        float a0 = v[g * 8 + 0] * sc, a1 = v[g * 8 + 1] * sc;
        float a2 = v[g * 8 + 2] * sc, a3 = v[g * 8 + 3] * sc;
        float a4 = v[g * 8 + 4] * sc, a5 = v[g * 8 + 5] * sc;
        float a6 = v[g * 8 + 6] * sc, a7 = v[g * 8 + 7] * sc;
        *(uint4*)(o + g * 8) = make_uint4(cvt2(a1, a0), cvt2(a3, a2), cvt2(a5, a4), cvt2(a7, a6));
    }
}

// ---------------- flash attention (R9/R15 verbatim) ----------------
__global__ void __launch_bounds__(256, 2) attn_kernel(
    const __half* __restrict__ qh, const __half* __restrict__ kh,
    const __half* __restrict__ vh, const float* __restrict__ temp,
    float* __restrict__ out)
{
    __shared__ __align__(16) char arena[43008];
    __half* Qs = (__half*)arena;
    __half* KsBuf[2] = { (__half*)(arena + 14336), (__half*)(arena + 21504) };
    __half* VsBuf[2] = { (__half*)(arena + 28672), (__half*)(arena + 35584) };
    float*  lred = (float*)(arena + 42496);
    float*  Ored = (float*)arena;

    const int t    = threadIdx.x;
    const int lane = t & 31;
    const int wid  = t >> 5;
    const int wi   = wid & 3;
    const int wj   = wid >> 2;
    const int i0   = wi * 32;
    const int r    = lane >> 2;
    const int cc   = lane & 3;

    const int bh   = blockIdx.y;
    const int b    = bh >> 2;
    const int head = bh & 3;
    const int n0   = blockIdx.x * 128;

    const __half* qb = qh + (size_t)bh * NSP * HD;
    const __half* kb = kh + (size_t)bh * NSP * HD;
    const __half* vb = vh + ((size_t)b * CH + head * HD) * NSP;
    const float   cbias = fabsf(temp[head]) * L2E;

#pragma unroll
    for (int e = 0; e < 3; ++e) {
        int ch = t + e * 256, row = ch / 6, c = (ch % 6) * 8;
        cp16(&Qs[row * QKSTR + c], qb + ((size_t)(n0 + row)) * HD + c);
    }
    {
        int row = t / 6, c = (t % 6) * 8;
        cp16(&KsBuf[0][row * QKSTR + c], kb + (size_t)row * HD + c);
    }
    if (t < 128) {
        int ch = t + 256, row = ch / 6, c = (ch % 6) * 8;
        cp16(&KsBuf[0][row * QKSTR + c], kb + (size_t)row * HD + c);
    }
    {
        int row = t >> 3, c = (t & 7) * 8;
        cp16(&VsBuf[0][row * VSTR + c], vb + (size_t)row * NSP + c);
    }
    if (t < 128) {
        int ch = t + 256, row = ch >> 3, c = (ch & 7) * 8;
        cp16(&VsBuf[0][row * VSTR + c], vb + (size_t)row * NSP + c);
    }
    cp_commit();

    float oacc[2][6][4];
#pragma unroll
    for (int mt = 0; mt < 2; ++mt)
#pragma unroll
        for (int nt = 0; nt < 6; ++nt)
#pragma unroll
            for (int e = 0; e < 4; ++e) oacc[mt][nt][e] = 0.f;
    float l_lo[2] = {0.f, 0.f}, l_hi[2] = {0.f, 0.f};

    uint32_t qa[2][3][4];

    const int krow0 = t / 6,          kc0 = (t % 6) * 8;
    const int krow1 = (t + 256) / 6,  kc1 = ((t + 256) % 6) * 8;
    const int vrow0 = t >> 3,         vc0 = (t & 7) * 8;
    const int vrow1 = (t + 256) >> 3, vc1 = ((t + 256) & 7) * 8;

    for (int it = 0; it < NSP / 64; ++it) {
        const int cur = it & 1;
        const __half* Kc = KsBuf[cur];
        const __half* Vc = VsBuf[cur];
        const bool has_next = (it < NSP / 64 - 1);

        cp_wait0();
        __syncthreads();

        if (it == 0) {
#pragma unroll
            for (int mt = 0; mt < 2; ++mt)
#pragma unroll
                for (int ks = 0; ks < 3; ++ks)
                    ldsm_x4(qa[mt][ks][0], qa[mt][ks][1], qa[mt][ks][2], qa[mt][ks][3],
                            &Qs[(i0 + mt * 16 + (lane & 15)) * QKSTR + ks * 16 + ((lane >> 4) << 3)]);
        }

        if (has_next) {
            const int nb = cur ^ 1;
            const int m0n = (it + 1) * 64;
            cp16(&KsBuf[nb][krow0 * QKSTR + kc0], kb + ((size_t)(m0n + krow0)) * HD + kc0);
            if (t < 128)
                cp16(&KsBuf[nb][krow1 * QKSTR + kc1], kb + ((size_t)(m0n + krow1)) * HD + kc1);
            cp16(&VsBuf[nb][vrow0 * VSTR + vc0], vb + (size_t)vrow0 * NSP + m0n + vc0);
            if (t < 128)
                cp16(&VsBuf[nb][vrow1 * VSTR + vc1], vb + (size_t)vrow1 * NSP + m0n + vc1);
            cp_commit();
        }

        float sacc[2][4][4];
#pragma unroll
        for (int mt = 0; mt < 2; ++mt)
#pragma unroll
            for (int jj = 0; jj < 4; ++jj)
#pragma unroll
                for (int e = 0; e < 4; ++e) sacc[mt][jj][e] = 0.f;

#pragma unroll
        for (int ks = 0; ks < 3; ++ks) {
#pragma unroll
            for (int p = 0; p < 2; ++p) {
                uint32_t b0, b1, b2, b3;
                int row = wj * 32 + p * 16 + ((lane >> 4) << 3) + (lane & 7);
                int col = ks * 16 + (lane & 8);
                ldsm_x4(b0, b1, b2, b3, &Kc[row * QKSTR + col]);
#pragma unroll
                for (int mt = 0; mt < 2; ++mt) {
                    mma16816(sacc[mt][2 * p],     qa[mt][ks][0], qa[mt][ks][1],
                                                  qa[mt][ks][2], qa[mt][ks][3], b0, b1);
                    mma16816(sacc[mt][2 * p + 1], qa[mt][ks][0], qa[mt][ks][1],
                                                  qa[mt][ks][2], qa[mt][ks][3], b2, b3);
                }
            }
        }

        uint32_t plo[2][4], phi[2][4];
#pragma unroll
        for (int mt = 0; mt < 2; ++mt) {
            uint32_t sum_lo = 0, sum_hi = 0;
#pragma unroll
            for (int jj = 0; jj < 4; ++jj) {
                plo[mt][jj] = ex2h2(cvt2(sacc[mt][jj][1] - cbias, sacc[mt][jj][0] - cbias));
                phi[mt][jj] = ex2h2(cvt2(sacc[mt][jj][3] - cbias, sacc[mt][jj][2] - cbias));
                sum_lo = hadd2(sum_lo, plo[mt][jj]);
                sum_hi = hadd2(sum_hi, phi[mt][jj]);
            }
            float2 f0 = h22f2(sum_lo); l_lo[mt] += f0.x + f0.y;
            float2 f1 = h22f2(sum_hi); l_hi[mt] += f1.x + f1.y;
        }

#pragma unroll
        for (int nt = 0; nt < 6; ++nt) {
            uint32_t b0, b1, b2, b3;
            ldsm_x4(b0, b1, b2, b3,
                    &Vc[(nt * 8 + (lane & 7)) * VSTR + wj * 32 + ((lane >> 3) & 3) * 8]);
#pragma unroll
            for (int mt = 0; mt < 2; ++mt) {
                mma16816(oacc[mt][nt], plo[mt][0], phi[mt][0], plo[mt][1], phi[mt][1], b0, b1);
                mma16816(oacc[mt][nt], plo[mt][2], phi[mt][2], plo[mt][3], phi[mt][3], b2, b3);
            }
        }
        __syncthreads();
    }

#pragma unroll
    for (int mt = 0; mt < 2; ++mt) {
        l_lo[mt] += __shfl_xor_sync(0xffffffffu, l_lo[mt], 1);
        l_lo[mt] += __shfl_xor_sync(0xffffffffu, l_lo[mt], 2);
        l_hi[mt] += __shfl_xor_sync(0xffffffffu, l_hi[mt], 1);
        l_hi[mt] += __shfl_xor_sync(0xffffffffu, l_hi[mt], 2);
    }
    if (wj == 1) {
#pragma unroll
        for (int mt = 0; mt < 2; ++mt) {
            const int ib = i0 + mt * 16;
            if (cc == 0) {
                lred[ib + r]     = l_lo[mt];
                lred[ib + r + 8] = l_hi[mt];
            }
#pragma unroll
            for (int nt = 0; nt < 6; ++nt) {
                int d = nt * 8 + 2 * cc;
                *(float2*)&Ored[(ib + r) * ORST + d]     = make_float2(oacc[mt][nt][0], oacc[mt][nt][1]);
                *(float2*)&Ored[(ib + r + 8) * ORST + d] = make_float2(oacc[mt][nt][2], oacc[mt][nt][3]);
            }
        }
    }
    __syncthreads();
    if (wj == 0) {
        float* ob = out + ((size_t)(b * CH) + head * HD) * NSP + n0;
#pragma unroll
        for (int mt = 0; mt < 2; ++mt) {
            const int ib = i0 + mt * 16;
            const float linv_lo = 1.f / (l_lo[mt] + lred[ib + r]);
            const float linv_hi = 1.f / (l_hi[mt] + lred[ib + r + 8]);
#pragma unroll
            for (int nt = 0; nt < 6; ++nt) {
                int d = nt * 8 + 2 * cc;
                float2 p0 = *(const float2*)&Ored[(ib + r) * ORST + d];
                float2 p1 = *(const float2*)&Ored[(ib + r + 8) * ORST + d];
                ob[(size_t)d * NSP + ib + r]           = (oacc[mt][nt][0] + p0.x) * linv_lo;
                ob[(size_t)(d + 1) * NSP + ib + r]     = (oacc[mt][nt][1] + p0.y) * linv_lo;
                ob[(size_t)d * NSP + ib + r + 8]       = (oacc[mt][nt][2] + p1.x) * linv_hi;
                ob[(size_t)(d + 1) * NSP + ib + r + 8] = (oacc[mt][nt][3] + p1.y) * linv_hi;
            }
        }
    }
}

// ---------------- launcher (R15 set; dwconv/normh fp16 interface) ----------------
extern "C" void kernel_launch(void* const* d_in, const int* in_sizes, int n_in,
                              void* d_out, int out_size)
{
    const float* x      = (const float*)d_in[0];
    const float* w_qkv  = (const float*)d_in[1];
    const float* b_qkv  = (const float*)d_in[2];
    const float* w_dw   = (const float*)d_in[3];
    const float* b_dw   = (const float*)d_in[4];
    const float* w_proj = (const float*)d_in[5];
    const float* b_proj = (const float*)d_in[6];
    const float* temp   = (const float*)d_in[7];
    float* out = (float*)d_out;

    float*  qkv1; cudaGetSymbolAddress((void**)&qkv1, g_qkv);
    __half* qk16; cudaGetSymbolAddress((void**)&qk16, g_qk16);
    float*  att;  cudaGetSymbolAddress((void**)&att,  g_att);
    __half* qhp;  cudaGetSymbolAddress((void**)&qhp,  g_qh);
    __half* khp;  cudaGetSymbolAddress((void**)&khp,  g_kh);
    __half* vhp;  cudaGetSymbolAddress((void**)&vhp,  g_vh);

    conv1x1_tc_kernel<<<dim3(NSP / 64, C3 / 64, B2), 256>>>(x, w_qkv, b_qkv, qkv1, C3, CH);
    dwconv_kernel<<<dim3(B2 * C3, NSP / 1024), 256>>>(qkv1, w_dw, b_dw, qk16, vhp);
    normh_kernel<<<dim3(NSP / 128, B2 * HEADS, 2), 128>>>(qk16, qhp, khp, temp);
    attn_kernel<<<dim3(NSP / 128, B2 * HEADS), 256>>>(qhp, khp, vhp, temp, att);
    conv1x1_tc_kernel<<<dim3(NSP / 64, CH / 64, B2), 256>>>(att, w_proj, b_proj, out, CH, CH);
}